// round 14
// baseline (speedup 1.0000x reference)
#include <cuda_runtime.h>
#include <math.h>
#include <stdint.h>

// ---------------- problem constants ----------------
#define EDG   262144
#define BGR   8
#define NNODE 512
#define NDIM  128
#define EDIM  64
#define GDIM  32
#define FIN   320
#define H1D   256
#define AHD   64
#define KW    320            // GEMM1 K after LN-fold
#define NW    320            // GEMM1 N (H1D + AHD)
#define OUTD  64
#define NH    4
#define NSEG  (BGR*NNODE)

// 3-stage smem: A XOR-swizzled (no pad, 128x32 u32), B padded (32x68 u32)
#define AST   4096           // u32 per A stage
#define SBP   68             // padded B row stride (u32)
#define BST   (32*SBP)       // 2176 u32 per B stage
#define DYN3  (3*(AST+BST)*4) // 75264 B  (x3 CTAs = 225792 <= 228KB)

// ---------------- device scratch ----------------
__device__ uint32_t g_h[(size_t)EDG * H1D];    // silu hidden as tf32 bits
__device__ uint32_t g_Wtf[KW * NW];            // ln_g-scaled [W1|A1], tf32 bits
__device__ uint32_t g_W2tf[H1D * OUTD];        // W2, tf32 bits
__device__ float    g_u[NW];
__device__ float    g_vb[NW];
__device__ float    g_gg[BGR * NW];
__device__ float    g_ae[EDG * NH];
__device__ float    g_den[NSEG * NH];
__device__ float    g_invden[NSEG * NH];

// ---------------- helpers ----------------
__device__ __forceinline__ uint32_t f2tf(float f) {
    uint32_t r;
    asm("cvt.rna.tf32.f32 %0, %1;" : "=r"(r) : "f"(f));
    return r;
}
__device__ __forceinline__ void mma_tf32(float c[4],
                                         uint32_t a0, uint32_t a1, uint32_t a2, uint32_t a3,
                                         uint32_t b0, uint32_t b1)
{
    asm volatile(
        "mma.sync.aligned.m16n8k8.row.col.f32.tf32.tf32.f32 "
        "{%0,%1,%2,%3}, {%4,%5,%6,%7}, {%8,%9}, {%0,%1,%2,%3};"
        : "+f"(c[0]), "+f"(c[1]), "+f"(c[2]), "+f"(c[3])
        : "r"(a0), "r"(a1), "r"(a2), "r"(a3), "r"(b0), "r"(b1));
}
__device__ __forceinline__ float silu_f(float v) { return v / (1.f + __expf(-v)); }

#define CP16(dst_u32, src_ptr) \
    asm volatile("cp.async.cg.shared.global [%0], [%1], 16;" :: "r"(dst_u32), "l"(src_ptr))
#define CP_COMMIT() asm volatile("cp.async.commit_group;" ::: "memory")
#define CP_WAIT1()  asm volatile("cp.async.wait_group 1;" ::: "memory")

__device__ __forceinline__ float wcat(const float* W1, const float* A1, int k, int n) {
    return (n < H1D) ? W1[k * H1D + n] : A1[k * AHD + (n - H1D)];
}

// ---------------- prep ----------------
__global__ void prep_kernel(const float* __restrict__ W1, const float* __restrict__ A1,
                            const float* __restrict__ W2, const float* __restrict__ ln_g,
                            float* __restrict__ pooled)
{
    int i = blockIdx.x * blockDim.x + threadIdx.x;
    if (i < KW * NW) {
        int k = i / NW, n = i % NW;
        g_Wtf[i] = f2tf(ln_g[k] * wcat(W1, A1, k, n));
    }
    if (i < H1D * OUTD) g_W2tf[i] = f2tf(W2[i]);
    if (i < NSEG * NH) g_den[i] = 0.f;
    if (i < NSEG * OUTD) pooled[i] = 0.f;
}

__global__ void prep2_kernel(const float* __restrict__ W1, const float* __restrict__ A1,
                             const float* __restrict__ b1, const float* __restrict__ ab1,
                             const float* __restrict__ ln_g, const float* __restrict__ ln_b,
                             const float* __restrict__ globs)
{
    int n = blockIdx.x * 32 + threadIdx.x;
    if (n >= NW) return;
    float u = 0.f, vb = 0.f;
    for (int k = 0; k < KW; k++) {
        float w = wcat(W1, A1, k, n);
        u  += ln_g[k] * w;
        vb += ln_b[k] * w;
    }
    vb += (n < H1D) ? b1[n] : ab1[n - H1D];
    g_u[n] = u;
    g_vb[n] = vb;
    for (int b = 0; b < BGR; b++) {
        float s = 0.f;
        for (int j = 0; j < GDIM; j++)
            s += globs[b * GDIM + j] * wcat(W1, A1, KW + j, n);
        g_gg[b * NW + n] = s;
    }
}

// ================= fused gather + GEMM1, 3-stage cp.async, 3 CTAs/SM =================
__global__ void __launch_bounds__(256, 3) gemm1_fused(const float* __restrict__ nodes,
                                                      const float* __restrict__ edges0,
                                                      const int* __restrict__ bidx,
                                                      const int* __restrict__ sidx,
                                                      const int* __restrict__ ridx,
                                                      const float* __restrict__ A2,
                                                      const float* __restrict__ ab2)
{
    extern __shared__ uint32_t dyn[];
    uint32_t* Asm = dyn;                 // 3 * AST
    uint32_t* Bsm = dyn + 3 * AST;       // 3 * BST
    // post-mainloop aliases into stage-0 A buffer (safe after barrier):
    float2* sstat = reinterpret_cast<float2*>(dyn);           // 128 * float2
    float (*slog)[NH] = reinterpret_cast<float (*)[NH]>(dyn + 256); // 128 x 4

    const int t = threadIdx.x, lane = t & 31, wid = t >> 5;
    const int g4 = lane >> 2, t4 = lane & 3;
    const int wm = (wid & 3) * 32, wn = (wid >> 2) * 32;
    const int m0 = blockIdx.y * 128, n0 = blockIdx.x * 64;
    const bool is_attn = (blockIdx.x == 4);

    float c[2][4][4];
#pragma unroll
    for (int mi = 0; mi < 2; mi++)
#pragma unroll
        for (int ni = 0; ni < 4; ni++)
#pragma unroll
            for (int q = 0; q < 4; q++) c[mi][ni][q] = 0.f;

    // staging geometry: 8 threads per row, rows r0l+32i
    const int ac4 = t & 7;
    const int r0l = t >> 3;
    int soff[4], roff[4];
#pragma unroll
    for (int i = 0; i < 4; i++) {
        int e = m0 + r0l + 32 * i;
        int b = bidx[e];
        soff[i] = (b * NNODE + sidx[e]) * NDIM;
        roff[i] = (b * NNODE + ridx[e]) * NDIM;
    }
    // swizzled u32 offsets within an A stage
    uint32_t aoff[4];
#pragma unroll
    for (int i = 0; i < 4; i++)
        aoff[i] = (uint32_t)(r0l + 32 * i) * 32 + ((ac4 ^ (r0l & 7)) << 2);

    int brow[2], bc4[2];
#pragma unroll
    for (int i = 0; i < 2; i++) { int idx = t + 256 * i; brow[i] = idx >> 4; bc4[i] = idx & 15; }

    const uint32_t AshG = (uint32_t)__cvta_generic_to_shared(Asm);
    const uint32_t BshG = (uint32_t)__cvta_generic_to_shared(Bsm);

    auto issue = [&](int it) {
        int k0 = it * 32;
        int buf = it % 3;
        uint32_t ab = AshG + buf * (AST * 4);
        uint32_t bb = BshG + buf * (BST * 4);
        int kq = k0 + ac4 * 4;
        if (k0 < 64) {
#pragma unroll
            for (int i = 0; i < 4; i++)
                CP16(ab + aoff[i] * 4, edges0 + (size_t)(m0 + r0l + 32 * i) * EDIM + kq);
        } else if (k0 < 192) {
#pragma unroll
            for (int i = 0; i < 4; i++)
                CP16(ab + aoff[i] * 4, nodes + soff[i] + (kq - 64));
        } else {
#pragma unroll
            for (int i = 0; i < 4; i++)
                CP16(ab + aoff[i] * 4, nodes + roff[i] + (kq - 192));
        }
#pragma unroll
        for (int i = 0; i < 2; i++)
            CP16(bb + (brow[i] * SBP + bc4[i] * 4) * 4,
                 &g_Wtf[(size_t)(k0 + brow[i]) * NW + n0 + bc4[i] * 4]);
    };

    float s1[4] = {0.f, 0.f, 0.f, 0.f}, s2[4] = {0.f, 0.f, 0.f, 0.f};

    issue(0); CP_COMMIT();
    issue(1); CP_COMMIT();

    constexpr int NIT = KW / 32;   // 10
#pragma unroll 1
    for (int it = 0; it < NIT; it++) {
        CP_WAIT1();
        __syncthreads();
        // buffer (it+2)%3 was last read in compute(it-1), finished before this barrier
        if (it + 2 < NIT) issue(it + 2);
        CP_COMMIT();

        const int buf = it % 3;
        const uint32_t* Ab = Asm + buf * AST;
        const uint32_t* Bb = Bsm + buf * BST;

        // LayerNorm stats readback (this thread's own swizzled slots)
#pragma unroll
        for (int i = 0; i < 4; i++) {
            float4 a = *reinterpret_cast<const float4*>(&Ab[aoff[i]]);
            s1[i] += a.x + a.y + a.z + a.w;
            s2[i] += a.x * a.x + a.y * a.y + a.z * a.z + a.w * a.w;
        }

#pragma unroll
        for (int ks = 0; ks < 4; ks++) {
            const int kk = ks * 8;
            uint32_t a[2][4], b[4][2];
#pragma unroll
            for (int mi = 0; mi < 2; mi++) {
                int r1 = (wm + mi * 16 + g4) * 32;
                int r2 = r1 + 8 * 32;
                int c0 = (((2 * ks)     ^ g4) << 2) + t4;
                int c1 = (((2 * ks + 1) ^ g4) << 2) + t4;
                a[mi][0] = Ab[r1 + c0];
                a[mi][1] = Ab[r2 + c0];
                a[mi][2] = Ab[r1 + c1];
                a[mi][3] = Ab[r2 + c1];
            }
#pragma unroll
            for (int ni = 0; ni < 4; ni++) {
                int nb = wn + ni * 8 + g4;
                b[ni][0] = Bb[(kk + t4) * SBP + nb];
                b[ni][1] = Bb[(kk + t4 + 4) * SBP + nb];
            }
#pragma unroll
            for (int mi = 0; mi < 2; mi++)
#pragma unroll
                for (int ni = 0; ni < 4; ni++)
                    mma_tf32(c[mi][ni], a[mi][0], a[mi][1], a[mi][2], a[mi][3],
                             b[ni][0], b[ni][1]);
        }
    }

    // ---- finalize LN stats (aliased smem: barrier before reuse of stage 0) ----
#pragma unroll
    for (int off = 4; off > 0; off >>= 1)
#pragma unroll
        for (int i = 0; i < 4; i++) {
            s1[i] += __shfl_xor_sync(0xffffffffu, s1[i], off);
            s2[i] += __shfl_xor_sync(0xffffffffu, s2[i], off);
        }
    __syncthreads();   // everyone done reading stage-0 smem
    if ((t & 7) == 0) {
#pragma unroll
        for (int i = 0; i < 4; i++) {
            float mu  = s1[i] * (1.f / FIN);
            float var = s2[i] * (1.f / FIN) - mu * mu;
            sstat[r0l + 32 * i] = make_float2(mu, rsqrtf(var + 1e-5f));
        }
    }
    if (is_attn && t < 128)
        *reinterpret_cast<float4*>(&slog[t][0]) = make_float4(0.f, 0.f, 0.f, 0.f);
    __syncthreads();

    float mu[4], rs[4];
    int   gi[4];
#pragma unroll
    for (int q = 0; q < 4; q++) {
        int rl = wm + g4 + 8 * q;
        float2 st = sstat[rl];
        mu[q] = st.x; rs[q] = st.y;
        gi[q] = bidx[m0 + rl];
    }

    if (!is_attn) {
#pragma unroll
        for (int mi = 0; mi < 2; mi++) {
#pragma unroll
            for (int ni = 0; ni < 4; ni++) {
                int n = n0 + wn + ni * 8 + 2 * t4;
                float2 u2  = *reinterpret_cast<const float2*>(&g_u[n]);
                float2 vb2 = *reinterpret_cast<const float2*>(&g_vb[n]);
#pragma unroll
                for (int hf = 0; hf < 2; hf++) {
                    int q = 2 * mi + hf;
                    float2 gg2 = *reinterpret_cast<const float2*>(&g_gg[gi[q] * NW + n]);
                    float o0 = rs[q] * (c[mi][ni][2 * hf]     - mu[q] * u2.x) + vb2.x + gg2.x;
                    float o1 = rs[q] * (c[mi][ni][2 * hf + 1] - mu[q] * u2.y) + vb2.y + gg2.y;
                    int rr = m0 + wm + mi * 16 + g4 + 8 * hf;
                    *reinterpret_cast<uint2*>(&g_h[(size_t)rr * H1D + n]) =
                        make_uint2(f2tf(silu_f(o0)), f2tf(silu_f(o1)));
                }
            }
        }
    } else {
        float pl[2][2][NH];
#pragma unroll
        for (int mi = 0; mi < 2; mi++)
#pragma unroll
            for (int hf = 0; hf < 2; hf++)
#pragma unroll
                for (int h = 0; h < NH; h++) pl[mi][hf][h] = 0.f;

#pragma unroll
        for (int mi = 0; mi < 2; mi++) {
#pragma unroll
            for (int ni = 0; ni < 4; ni++) {
                int nl = wn + ni * 8 + 2 * t4;
                int n  = H1D + nl;
                float2 u2  = *reinterpret_cast<const float2*>(&g_u[n]);
                float2 vb2 = *reinterpret_cast<const float2*>(&g_vb[n]);
                float4 a20 = *reinterpret_cast<const float4*>(&A2[nl * NH]);
                float4 a21 = *reinterpret_cast<const float4*>(&A2[(nl + 1) * NH]);
#pragma unroll
                for (int hf = 0; hf < 2; hf++) {
                    int q = 2 * mi + hf;
                    float2 gg2 = *reinterpret_cast<const float2*>(&g_gg[gi[q] * NW + n]);
                    float v0 = silu_f(rs[q] * (c[mi][ni][2 * hf]     - mu[q] * u2.x) + vb2.x + gg2.x);
                    float v1 = silu_f(rs[q] * (c[mi][ni][2 * hf + 1] - mu[q] * u2.y) + vb2.y + gg2.y);
                    pl[mi][hf][0] += v0 * a20.x + v1 * a21.x;
                    pl[mi][hf][1] += v0 * a20.y + v1 * a21.y;
                    pl[mi][hf][2] += v0 * a20.z + v1 * a21.z;
                    pl[mi][hf][3] += v0 * a20.w + v1 * a21.w;
                }
            }
        }
#pragma unroll
        for (int mi = 0; mi < 2; mi++)
#pragma unroll
            for (int hf = 0; hf < 2; hf++) {
                int rl = wm + mi * 16 + g4 + hf * 8;
#pragma unroll
                for (int h = 0; h < NH; h++)
                    atomicAdd(&slog[rl][h], pl[mi][hf][h]);
            }
        __syncthreads();

        if (t < 128) {
            int e = m0 + t;
            float4 l = *reinterpret_cast<float4*>(&slog[t][0]);
            float ae0 = __expf((l.x + ab2[0]) * 0.125f);
            float ae1 = __expf((l.y + ab2[1]) * 0.125f);
            float ae2 = __expf((l.z + ab2[2]) * 0.125f);
            float ae3 = __expf((l.w + ab2[3]) * 0.125f);
            *reinterpret_cast<float4*>(&g_ae[(size_t)e * NH]) = make_float4(ae0, ae1, ae2, ae3);
            int seg = bidx[e] * NNODE + ridx[e];
            atomicAdd(&g_den[seg * NH + 0], ae0);
            atomicAdd(&g_den[seg * NH + 1], ae1);
            atomicAdd(&g_den[seg * NH + 2], ae2);
            atomicAdd(&g_den[seg * NH + 3], ae3);
        }
    }
}

__global__ void invden_kernel()
{
    int i = blockIdx.x * blockDim.x + threadIdx.x;
    if (i < NSEG * NH) {
        float d = g_den[i];
        g_invden[i] = (d > 0.f) ? (1.f / d) : 0.f;
    }
}

// ================= GEMM2 + residual + pool, 3-stage cp.async =================
__global__ void __launch_bounds__(256, 3) gemm2_fused(const float* __restrict__ b2,
                                                      const float* __restrict__ edges0,
                                                      const int* __restrict__ bidx,
                                                      const int* __restrict__ ridx,
                                                      float* __restrict__ Cout,
                                                      float* __restrict__ pooled)
{
    extern __shared__ uint32_t dyn[];
    uint32_t* Asm = dyn;
    uint32_t* Bsm = dyn + 3 * AST;

    constexpr int LDA = H1D, NTOT = OUTD;
    const int t = threadIdx.x, lane = t & 31, wid = t >> 5;
    const int g4 = lane >> 2, t4 = lane & 3;
    const int wm = (wid & 3) * 32, wn = (wid >> 2) * 32;
    const int m0 = blockIdx.y * 128;

    float c[2][4][4];
#pragma unroll
    for (int mi = 0; mi < 2; mi++)
#pragma unroll
        for (int ni = 0; ni < 4; ni++)
#pragma unroll
            for (int q = 0; q < 4; q++) c[mi][ni][q] = 0.f;

    const uint32_t* Ap = g_h + (size_t)m0 * LDA;

    const int ac4 = t & 7;
    const int r0l = t >> 3;
    uint32_t aoff[4];
#pragma unroll
    for (int i = 0; i < 4; i++)
        aoff[i] = (uint32_t)(r0l + 32 * i) * 32 + ((ac4 ^ (r0l & 7)) << 2);

    int brow[2], bc4[2];
#pragma unroll
    for (int i = 0; i < 2; i++) { int idx = t + 256 * i; brow[i] = idx >> 4; bc4[i] = idx & 15; }

    const uint32_t AshG = (uint32_t)__cvta_generic_to_shared(Asm);
    const uint32_t BshG = (uint32_t)__cvta_generic_to_shared(Bsm);

    auto issue = [&](int it) {
        int k0 = it * 32;
        int buf = it % 3;
        uint32_t ab = AshG + buf * (AST * 4);
        uint32_t bb = BshG + buf * (BST * 4);
#pragma unroll
        for (int i = 0; i < 4; i++)
            CP16(ab + aoff[i] * 4, Ap + (size_t)(r0l + 32 * i) * LDA + k0 + ac4 * 4);
#pragma unroll
        for (int i = 0; i < 2; i++)
            CP16(bb + (brow[i] * SBP + bc4[i] * 4) * 4,
                 &g_W2tf[(size_t)(k0 + brow[i]) * NTOT + bc4[i] * 4]);
    };

    issue(0); CP_COMMIT();
    issue(1); CP_COMMIT();

    constexpr int NIT = H1D / 32;   // 8
#pragma unroll 1
    for (int it = 0; it < NIT; it++) {
        CP_WAIT1();
        __syncthreads();
        if (it + 2 < NIT) issue(it + 2);
        CP_COMMIT();

        const int buf = it % 3;
        const uint32_t* Ab = Asm + buf * AST;
        const uint32_t* Bb = Bsm + buf * BST;

#pragma unroll
        for (int ks = 0; ks < 4; ks++) {
            const int kk = ks * 8;
            uint32_t a[2][4], b[4][2];
#pragma unroll
            for (int mi = 0; mi < 2; mi++) {
                int r1 = (wm + mi * 16 + g4) * 32;
                int r2 = r1 + 8 * 32;
                int c0 = (((2 * ks)     ^ g4) << 2) + t4;
                int c1 = (((2 * ks + 1) ^ g4) << 2) + t4;
                a[mi][0] = Ab[r1 + c0];
                a[mi][1] = Ab[r2 + c0];
                a[mi][2] = Ab[r1 + c1];
                a[mi][3] = Ab[r2 + c1];
            }
#pragma unroll
            for (int ni = 0; ni < 4; ni++) {
                int nb = wn + ni * 8 + g4;
                b[ni][0] = Bb[(kk + t4) * SBP + nb];
                b[ni][1] = Bb[(kk + t4 + 4) * SBP + nb];
            }
#pragma unroll
            for (int mi = 0; mi < 2; mi++)
#pragma unroll
                for (int ni = 0; ni < 4; ni++)
                    mma_tf32(c[mi][ni], a[mi][0], a[mi][1], a[mi][2], a[mi][3],
                             b[ni][0], b[ni][1]);
        }
    }

    // per-row attention weights
    int   segr[2][2];
    float aw[2][2][NH];
#pragma unroll
    for (int mi = 0; mi < 2; mi++)
#pragma unroll
        for (int hf = 0; hf < 2; hf++) {
            int r = m0 + wm + mi * 16 + g4 + hf * 8;
            int seg = bidx[r] * NNODE + ridx[r];
            segr[mi][hf] = seg;
            float4 ae4 = *reinterpret_cast<const float4*>(&g_ae[(size_t)r * NH]);
            float4 iv4 = *reinterpret_cast<const float4*>(&g_invden[(size_t)seg * NH]);
            aw[mi][hf][0] = ae4.x * iv4.x;
            aw[mi][hf][1] = ae4.y * iv4.y;
            aw[mi][hf][2] = ae4.z * iv4.z;
            aw[mi][hf][3] = ae4.w * iv4.w;
        }

#pragma unroll
    for (int mi = 0; mi < 2; mi++) {
#pragma unroll
        for (int ni = 0; ni < 4; ni++) {
            int n = wn + ni * 8 + 2 * t4;
            int h = n >> 4;
            float bv0 = b2[n], bv1 = b2[n + 1];
            int rr0 = m0 + wm + mi * 16 + g4;
            int rr1 = rr0 + 8;
            float2 e0 = *reinterpret_cast<const float2*>(&edges0[(size_t)rr0 * NTOT + n]);
            float2 e1 = *reinterpret_cast<const float2*>(&edges0[(size_t)rr1 * NTOT + n]);
            float o00 = c[mi][ni][0] + bv0 + e0.x;
            float o01 = c[mi][ni][1] + bv1 + e0.y;
            float o10 = c[mi][ni][2] + bv0 + e1.x;
            float o11 = c[mi][ni][3] + bv1 + e1.y;
            *reinterpret_cast<float2*>(&Cout[(size_t)rr0 * NTOT + n]) = make_float2(o00, o01);
            *reinterpret_cast<float2*>(&Cout[(size_t)rr1 * NTOT + n]) = make_float2(o10, o11);
            float w0 = aw[mi][0][h], w1 = aw[mi][1][h];
            atomicAdd(&pooled[(size_t)segr[mi][0] * OUTD + n],     o00 * w0);
            atomicAdd(&pooled[(size_t)segr[mi][0] * OUTD + n + 1], o01 * w0);
            atomicAdd(&pooled[(size_t)segr[mi][1] * OUTD + n],     o10 * w1);
            atomicAdd(&pooled[(size_t)segr[mi][1] * OUTD + n + 1], o11 * w1);
        }
    }
}

// ---------------- entry ----------------
extern "C" void kernel_launch(void* const* d_in, const int* in_sizes, int n_in,
                              void* d_out, int out_size)
{
    const float* nodes  = (const float*)d_in[0];
    const float* edges0 = (const float*)d_in[1];
    const float* globs  = (const float*)d_in[2];
    const float* ln_g   = (const float*)d_in[3];
    const float* ln_b   = (const float*)d_in[4];
    const float* W1     = (const float*)d_in[5];
    const float* b1     = (const float*)d_in[6];
    const float* W2     = (const float*)d_in[7];
    const float* b2     = (const float*)d_in[8];
    const float* A1     = (const float*)d_in[9];
    const float* ab1    = (const float*)d_in[10];
    const float* A2     = (const float*)d_in[11];
    const float* ab2    = (const float*)d_in[12];
    const int*   bidx   = (const int*)d_in[13];
    const int*   sidx   = (const int*)d_in[14];
    const int*   ridx   = (const int*)d_in[15];

    float* out    = (float*)d_out;
    float* newe   = out;
    float* pooled = out + (size_t)EDG * OUTD;

    static bool attr_done = false;
    if (!attr_done) {
        cudaFuncSetAttribute(gemm1_fused, cudaFuncAttributeMaxDynamicSharedMemorySize, DYN3);
        cudaFuncSetAttribute(gemm2_fused, cudaFuncAttributeMaxDynamicSharedMemorySize, DYN3);
        attr_done = true;
    }

    prep_kernel<<<(NSEG * OUTD + 255) / 256, 256>>>(W1, A1, W2, ln_g, pooled);
    prep2_kernel<<<(NW + 31) / 32, 32>>>(W1, A1, b1, ab1, ln_g, ln_b, globs);
    gemm1_fused<<<dim3(5, EDG / 128), 256, DYN3>>>(nodes, edges0, bidx, sidx, ridx, A2, ab2);
    invden_kernel<<<(NSEG * NH + 255) / 256, 256>>>();
    gemm2_fused<<<dim3(1, EDG / 128), 256, DYN3>>>(b2, edges0, bidx, ridx, newe, pooled);
}

// round 16
// speedup vs baseline: 1.0815x; 1.0815x over previous
#include <cuda_runtime.h>
#include <cuda_fp16.h>
#include <math.h>
#include <stdint.h>

// ---------------- problem constants ----------------
#define EDG   262144
#define BGR   8
#define NNODE 512
#define NDIM  128
#define EDIM  64
#define GDIM  32
#define FIN   320
#define H1D   256
#define AHD   64
#define KW    320            // GEMM1 K after LN-fold
#define NW    320            // GEMM1 N (H1D + AHD)
#define OUTD  64
#define NH    4
#define NSEG  (BGR*NNODE)

// gemm1 smem (2-stage padded)
#define SA    36             // padded A row stride (u32)
#define SB    72             // padded B row stride (u32)
#define ASTRIDE (128*SA)
#define BSTRIDE (32*SB)
#define DYN_G1 ((2*(ASTRIDE+BSTRIDE))*4)   // 55296 B

// gemm2 smem (2-stage padded, fp16 packed)
#define SA2   36
#define SB2   36
#define A2STR (128*SA2)
#define B2STR (64*SB2)
#define DYN_G2 ((2*(A2STR+B2STR))*4)

// ---------------- device scratch ----------------
__device__ uint32_t g_h[(size_t)EDG * (H1D/2)];  // silu hidden, packed fp16x2
__device__ uint32_t g_Wtf[KW * NW];              // ln_g-scaled [W1|A1], tf32 bits, col-permuted
__device__ uint32_t g_W2h[OUTD * (H1D/2)];       // W2 transposed [n][k/2], fp16x2 pairs
__device__ float    g_u[NW];
__device__ float    g_vb[NW];
__device__ float    g_gg[BGR * NW];
__device__ float    g_ae[EDG * NH];
__device__ float    g_den[NSEG * NH];
__device__ float    g_invden[NSEG * NH];

// ---------------- helpers ----------------
__device__ __forceinline__ uint32_t f2tf(float f) {
    uint32_t r;
    asm("cvt.rna.tf32.f32 %0, %1;" : "=r"(r) : "f"(f));
    return r;
}
__device__ __forceinline__ uint32_t pack_h2(float lo, float hi) {
    __half2 h = __floats2half2_rn(lo, hi);   // x = lo (low 16 bits), y = hi
    return *reinterpret_cast<uint32_t*>(&h);
}
__device__ __forceinline__ void mma_tf32(float c[4],
                                         uint32_t a0, uint32_t a1, uint32_t a2, uint32_t a3,
                                         uint32_t b0, uint32_t b1)
{
    asm volatile(
        "mma.sync.aligned.m16n8k8.row.col.f32.tf32.tf32.f32 "
        "{%0,%1,%2,%3}, {%4,%5,%6,%7}, {%8,%9}, {%0,%1,%2,%3};"
        : "+f"(c[0]), "+f"(c[1]), "+f"(c[2]), "+f"(c[3])
        : "r"(a0), "r"(a1), "r"(a2), "r"(a3), "r"(b0), "r"(b1));
}
__device__ __forceinline__ void mma_f16(float c[4],
                                        uint32_t a0, uint32_t a1, uint32_t a2, uint32_t a3,
                                        uint32_t b0, uint32_t b1)
{
    asm volatile(
        "mma.sync.aligned.m16n8k16.row.col.f32.f16.f16.f32 "
        "{%0,%1,%2,%3}, {%4,%5,%6,%7}, {%8,%9}, {%0,%1,%2,%3};"
        : "+f"(c[0]), "+f"(c[1]), "+f"(c[2]), "+f"(c[3])
        : "r"(a0), "r"(a1), "r"(a2), "r"(a3), "r"(b0), "r"(b1));
}
__device__ __forceinline__ float silu_f(float v) { return v / (1.f + __expf(-v)); }

#define CP16(dst_u32, src_ptr) \
    asm volatile("cp.async.cg.shared.global [%0], [%1], 16;" :: "r"(dst_u32), "l"(src_ptr))
#define CP_COMMIT() asm volatile("cp.async.commit_group;" ::: "memory")
#define CP_WAIT0()  asm volatile("cp.async.wait_group 0;" ::: "memory")

__device__ __forceinline__ float wcat(const float* W1, const float* A1, int k, int n) {
    return (n < H1D) ? W1[k * H1D + n] : A1[k * AHD + (n - H1D)];
}

// column permutation within each 64-wide n-block (gemm1 B only)
__device__ __forceinline__ int perm_orig(int p) {
    int wn = p & 32;
    int r  = p & 31;
    int g4 = r >> 2, ni = r & 3;
    return wn + ni * 8 + g4;
}

// ---------------- prep ----------------
__global__ void prep_kernel(const float* __restrict__ W1, const float* __restrict__ A1,
                            const float* __restrict__ W2, const float* __restrict__ ln_g,
                            float* __restrict__ pooled)
{
    int i = blockIdx.x * blockDim.x + threadIdx.x;
    if (i < KW * NW) {
        int k = i / NW, np = i % NW;
        int n = (np & ~63) + perm_orig(np & 63);
        g_Wtf[i] = f2tf(ln_g[k] * wcat(W1, A1, k, n));
    }
    if (i < OUTD * (H1D / 2)) {
        int n = i / (H1D / 2), j = i % (H1D / 2);
        g_W2h[i] = pack_h2(W2[(2 * j) * OUTD + n], W2[(2 * j + 1) * OUTD + n]);
    }
    if (i < NSEG * NH) g_den[i] = 0.f;
    if (i < NSEG * OUTD) pooled[i] = 0.f;
}

__global__ void prep2_kernel(const float* __restrict__ W1, const float* __restrict__ A1,
                             const float* __restrict__ b1, const float* __restrict__ ab1,
                             const float* __restrict__ ln_g, const float* __restrict__ ln_b,
                             const float* __restrict__ globs)
{
    int n = blockIdx.x * 32 + threadIdx.x;
    if (n >= NW) return;
    float u = 0.f, vb = 0.f;
    for (int k = 0; k < KW; k++) {
        float w = wcat(W1, A1, k, n);
        u  += ln_g[k] * w;
        vb += ln_b[k] * w;
    }
    vb += (n < H1D) ? b1[n] : ab1[n - H1D];
    g_u[n] = u;
    g_vb[n] = vb;
    for (int b = 0; b < BGR; b++) {
        float s = 0.f;
        for (int j = 0; j < GDIM; j++)
            s += globs[b * GDIM + j] * wcat(W1, A1, KW + j, n);
        g_gg[b * NW + n] = s;
    }
}

// ================= fused gather + GEMM1 (tf32), 2-stage cp.async, permuted B =================
__global__ void __launch_bounds__(256, 3) gemm1_fused(const float* __restrict__ nodes,
                                                      const float* __restrict__ edges0,
                                                      const int* __restrict__ bidx,
                                                      const int* __restrict__ sidx,
                                                      const int* __restrict__ ridx,
                                                      const float* __restrict__ A2,
                                                      const float* __restrict__ ab2)
{
    extern __shared__ uint32_t dyn[];
    uint32_t* As = dyn;
    uint32_t* Bs = dyn + 2 * ASTRIDE;
    __shared__ float2 sstat[128];
    __shared__ float  slog[128][NH];

    const int t = threadIdx.x, lane = t & 31, wid = t >> 5;
    const int g4 = lane >> 2, t4 = lane & 3;
    const int wm = (wid & 3) * 32, wn = (wid >> 2) * 32;
    const int m0 = blockIdx.y * 128, n0 = blockIdx.x * 64;
    const bool is_attn = (blockIdx.x == 4);

    float c[2][4][4];
#pragma unroll
    for (int mi = 0; mi < 2; mi++)
#pragma unroll
        for (int ni = 0; ni < 4; ni++)
#pragma unroll
            for (int q = 0; q < 4; q++) c[mi][ni][q] = 0.f;

    const int ac4 = t & 7;
    const int r0l = t >> 3;
    int soff[4], roff[4];
#pragma unroll
    for (int i = 0; i < 4; i++) {
        int e = m0 + r0l + 32 * i;
        int b = bidx[e];
        soff[i] = (b * NNODE + sidx[e]) * NDIM;
        roff[i] = (b * NNODE + ridx[e]) * NDIM;
    }
    int brow[2], bc4[2];
#pragma unroll
    for (int i = 0; i < 2; i++) { int idx = t + 256 * i; brow[i] = idx >> 4; bc4[i] = idx & 15; }

    uint32_t aslot[4], bslot[2];
#pragma unroll
    for (int i = 0; i < 4; i++)
        aslot[i] = (uint32_t)__cvta_generic_to_shared(&As[(r0l + 32 * i) * SA + ac4 * 4]);
#pragma unroll
    for (int i = 0; i < 2; i++)
        bslot[i] = (uint32_t)__cvta_generic_to_shared(&Bs[brow[i] * SB + bc4[i] * 4]);

    auto issue = [&](int it) {
        int k0 = it * 32;
        uint32_t ab = (it & 1) * (ASTRIDE * 4);
        uint32_t bb = (it & 1) * (BSTRIDE * 4);
        int kq = k0 + ac4 * 4;
        if (k0 < 64) {
#pragma unroll
            for (int i = 0; i < 4; i++)
                CP16(aslot[i] + ab, edges0 + (size_t)(m0 + r0l + 32 * i) * EDIM + kq);
        } else if (k0 < 192) {
#pragma unroll
            for (int i = 0; i < 4; i++)
                CP16(aslot[i] + ab, nodes + soff[i] + (kq - 64));
        } else {
#pragma unroll
            for (int i = 0; i < 4; i++)
                CP16(aslot[i] + ab, nodes + roff[i] + (kq - 192));
        }
#pragma unroll
        for (int i = 0; i < 2; i++)
            CP16(bslot[i] + bb, &g_Wtf[(size_t)(k0 + brow[i]) * NW + n0 + bc4[i] * 4]);
    };

    float s1[4] = {0.f, 0.f, 0.f, 0.f}, s2[4] = {0.f, 0.f, 0.f, 0.f};

    issue(0); CP_COMMIT();

    constexpr int NIT = KW / 32;   // 10
#pragma unroll 1
    for (int it = 0; it < NIT; it++) {
        CP_WAIT0();
        __syncthreads();
        if (it + 1 < NIT) { issue(it + 1); CP_COMMIT(); }

        const int buf = it & 1;
        const uint32_t* Ab = As + buf * ASTRIDE;
        const uint32_t* Bb = Bs + buf * BSTRIDE;

        // LayerNorm stats readback
#pragma unroll
        for (int i = 0; i < 4; i++) {
            float4 a = *reinterpret_cast<const float4*>(&Ab[(r0l + 32 * i) * SA + ac4 * 4]);
            s1[i] += a.x + a.y + a.z + a.w;
            s2[i] += a.x * a.x + a.y * a.y + a.z * a.z + a.w * a.w;
        }

#pragma unroll
        for (int ks = 0; ks < 4; ks++) {
            const int kk = ks * 8;
            uint32_t a[2][4];
#pragma unroll
            for (int mi = 0; mi < 2; mi++) {
                int mb = wm + mi * 16;
                a[mi][0] = Ab[(mb + g4) * SA + kk + t4];
                a[mi][1] = Ab[(mb + g4 + 8) * SA + kk + t4];
                a[mi][2] = Ab[(mb + g4) * SA + kk + t4 + 4];
                a[mi][3] = Ab[(mb + g4 + 8) * SA + kk + t4 + 4];
            }
            uint4 bq0 = *reinterpret_cast<const uint4*>(&Bb[(kk + t4) * SB + wn + g4 * 4]);
            uint4 bq1 = *reinterpret_cast<const uint4*>(&Bb[(kk + t4 + 4) * SB + wn + g4 * 4]);
            uint32_t b0[4] = {bq0.x, bq0.y, bq0.z, bq0.w};
            uint32_t b1[4] = {bq1.x, bq1.y, bq1.z, bq1.w};
#pragma unroll
            for (int mi = 0; mi < 2; mi++)
#pragma unroll
                for (int ni = 0; ni < 4; ni++)
                    mma_tf32(c[mi][ni], a[mi][0], a[mi][1], a[mi][2], a[mi][3],
                             b0[ni], b1[ni]);
        }
        __syncthreads();
    }

    // ---- finalize LN stats ----
#pragma unroll
    for (int off = 4; off > 0; off >>= 1)
#pragma unroll
        for (int i = 0; i < 4; i++) {
            s1[i] += __shfl_xor_sync(0xffffffffu, s1[i], off);
            s2[i] += __shfl_xor_sync(0xffffffffu, s2[i], off);
        }
    if ((t & 7) == 0) {
#pragma unroll
        for (int i = 0; i < 4; i++) {
            float mu  = s1[i] * (1.f / FIN);
            float var = s2[i] * (1.f / FIN) - mu * mu;
            sstat[r0l + 32 * i] = make_float2(mu, rsqrtf(var + 1e-5f));
        }
    }
    if (is_attn && t < 128)
        *reinterpret_cast<float4*>(&slog[t][0]) = make_float4(0.f, 0.f, 0.f, 0.f);
    __syncthreads();

    float mu[4], rs[4];
    int   gi[4];
#pragma unroll
    for (int q = 0; q < 4; q++) {
        int rl = wm + g4 + 8 * q;
        float2 st = sstat[rl];
        mu[q] = st.x; rs[q] = st.y;
        gi[q] = bidx[m0 + rl];
    }

    if (!is_attn) {
#pragma unroll
        for (int mi = 0; mi < 2; mi++) {
#pragma unroll
            for (int ni = 0; ni < 4; ni++) {
                int n = n0 + wn + ni * 8 + 2 * t4;      // even
                float2 u2  = *reinterpret_cast<const float2*>(&g_u[n]);
                float2 vb2 = *reinterpret_cast<const float2*>(&g_vb[n]);
#pragma unroll
                for (int hf = 0; hf < 2; hf++) {
                    int q = 2 * mi + hf;
                    float2 gg2 = *reinterpret_cast<const float2*>(&g_gg[gi[q] * NW + n]);
                    float o0 = rs[q] * (c[mi][ni][2 * hf]     - mu[q] * u2.x) + vb2.x + gg2.x;
                    float o1 = rs[q] * (c[mi][ni][2 * hf + 1] - mu[q] * u2.y) + vb2.y + gg2.y;
                    int rr = m0 + wm + mi * 16 + g4 + 8 * hf;
                    g_h[(size_t)rr * (H1D / 2) + n / 2] = pack_h2(silu_f(o0), silu_f(o1));
                }
            }
        }
    } else {
        float pl[2][2][NH];
#pragma unroll
        for (int mi = 0; mi < 2; mi++)
#pragma unroll
            for (int hf = 0; hf < 2; hf++)
#pragma unroll
                for (int h = 0; h < NH; h++) pl[mi][hf][h] = 0.f;

#pragma unroll
        for (int mi = 0; mi < 2; mi++) {
#pragma unroll
            for (int ni = 0; ni < 4; ni++) {
                int nl = wn + ni * 8 + 2 * t4;
                int n  = H1D + nl;
                float2 u2  = *reinterpret_cast<const float2*>(&g_u[n]);
                float2 vb2 = *reinterpret_cast<const float2*>(&g_vb[n]);
                float4 a20 = *reinterpret_cast<const float4*>(&A2[nl * NH]);
                float4 a21 = *reinterpret_cast<const float4*>(&A2[(nl + 1) * NH]);
#pragma unroll
                for (int hf = 0; hf < 2; hf++) {
                    int q = 2 * mi + hf;
                    float2 gg2 = *reinterpret_cast<const float2*>(&g_gg[gi[q] * NW + n]);
                    float v0 = silu_f(rs[q] * (c[mi][ni][2 * hf]     - mu[q] * u2.x) + vb2.x + gg2.x);
                    float v1 = silu_f(rs[q] * (c[mi][ni][2 * hf + 1] - mu[q] * u2.y) + vb2.y + gg2.y);
                    pl[mi][hf][0] += v0 * a20.x + v1 * a21.x;
                    pl[mi][hf][1] += v0 * a20.y + v1 * a21.y;
                    pl[mi][hf][2] += v0 * a20.z + v1 * a21.z;
                    pl[mi][hf][3] += v0 * a20.w + v1 * a21.w;
                }
            }
        }
#pragma unroll
        for (int mi = 0; mi < 2; mi++)
#pragma unroll
            for (int hf = 0; hf < 2; hf++) {
                int rl = wm + mi * 16 + g4 + hf * 8;
#pragma unroll
                for (int h = 0; h < NH; h++)
                    atomicAdd(&slog[rl][h], pl[mi][hf][h]);
            }
        __syncthreads();

        if (t < 128) {
            int e = m0 + t;
            float4 l = *reinterpret_cast<float4*>(&slog[t][0]);
            float ae0 = __expf((l.x + ab2[0]) * 0.125f);
            float ae1 = __expf((l.y + ab2[1]) * 0.125f);
            float ae2 = __expf((l.z + ab2[2]) * 0.125f);
            float ae3 = __expf((l.w + ab2[3]) * 0.125f);
            *reinterpret_cast<float4*>(&g_ae[(size_t)e * NH]) = make_float4(ae0, ae1, ae2, ae3);
            int seg = bidx[e] * NNODE + ridx[e];
            atomicAdd(&g_den[seg * NH + 0], ae0);
            atomicAdd(&g_den[seg * NH + 1], ae1);
            atomicAdd(&g_den[seg * NH + 2], ae2);
            atomicAdd(&g_den[seg * NH + 3], ae3);
        }
    }
}

__global__ void invden_kernel()
{
    int i = blockIdx.x * blockDim.x + threadIdx.x;
    if (i < NSEG * NH) {
        float d = g_den[i];
        g_invden[i] = (d > 0.f) ? (1.f / d) : 0.f;
    }
}

// ================= GEMM2 (fp16 m16n8k16) + residual + pool =================
__global__ void __launch_bounds__(256, 3) gemm2_fused(const float* __restrict__ b2,
                                                      const float* __restrict__ edges0,
                                                      const int* __restrict__ bidx,
                                                      const int* __restrict__ ridx,
                                                      float* __restrict__ Cout,
                                                      float* __restrict__ pooled)
{
    extern __shared__ uint32_t dyn[];
    uint32_t* As = dyn;                  // 2 * A2STR
    uint32_t* Bs = dyn + 2 * A2STR;      // 2 * B2STR

    constexpr int LDA = H1D / 2;         // 128 u32 per h row
    constexpr int NTOT = OUTD;
    const int t = threadIdx.x, lane = t & 31, wid = t >> 5;
    const int g4 = lane >> 2, t4 = lane & 3;
    const int wm = (wid & 3) * 32, wn = (wid >> 2) * 32;
    const int m0 = blockIdx.y * 128;

    float c[2][4][4];
#pragma unroll
    for (int mi = 0; mi < 2; mi++)
#pragma unroll
        for (int ni = 0; ni < 4; ni++)
#pragma unroll
            for (int q = 0; q < 4; q++) c[mi][ni][q] = 0.f;

    const uint32_t* Ap = g_h + (size_t)m0 * LDA;

    const int ac4 = t & 7;
    const int r0l = t >> 3;
    int brow2[2], bc2[2];
#pragma unroll
    for (int i = 0; i < 2; i++) { int idx = t + 256 * i; brow2[i] = idx >> 3; bc2[i] = idx & 7; }

    uint32_t aslot[4], bslot[2];
#pragma unroll
    for (int i = 0; i < 4; i++)
        aslot[i] = (uint32_t)__cvta_generic_to_shared(&As[(r0l + 32 * i) * SA2 + ac4 * 4]);
#pragma unroll
    for (int i = 0; i < 2; i++)
        bslot[i] = (uint32_t)__cvta_generic_to_shared(&Bs[brow2[i] * SB2 + bc2[i] * 4]);

    auto issue = [&](int it) {
        int k0 = it * 32;                 // u32 offset (64 fp16 cols)
        uint32_t ab = (it & 1) * (A2STR * 4);
        uint32_t bb = (it & 1) * (B2STR * 4);
#pragma unroll
        for (int i = 0; i < 4; i++)
            CP16(aslot[i] + ab, Ap + (size_t)(r0l + 32 * i) * LDA + k0 + ac4 * 4);
#pragma unroll
        for (int i = 0; i < 2; i++)
            CP16(bslot[i] + bb, &g_W2h[(size_t)brow2[i] * LDA + k0 + bc2[i] * 4]);
    };

    issue(0); CP_COMMIT();

    constexpr int NIT = 4;               // 256 fp16 k / 64 per stage
#pragma unroll 1
    for (int it = 0; it < NIT; it++) {
        CP_WAIT0();
        __syncthreads();
        if (it + 1 < NIT) { issue(it + 1); CP_COMMIT(); }

        const int buf = it & 1;
        const uint32_t* Ab = As + buf * A2STR;
        const uint32_t* Bb = Bs + buf * B2STR;

#pragma unroll
        for (int ks = 0; ks < 4; ks++) {        // 4 k16-slices per stage
            const int kk = ks * 8;
            uint32_t a[2][4], b[4][2];
#pragma unroll
            for (int mi = 0; mi < 2; mi++) {
                int mb = wm + mi * 16;
                a[mi][0] = Ab[(mb + g4) * SA2 + kk + t4];
                a[mi][1] = Ab[(mb + g4 + 8) * SA2 + kk + t4];
                a[mi][2] = Ab[(mb + g4) * SA2 + kk + t4 + 4];
                a[mi][3] = Ab[(mb + g4 + 8) * SA2 + kk + t4 + 4];
            }
#pragma unroll
            for (int ni = 0; ni < 4; ni++) {
                int nb = wn + ni * 8 + g4;
                b[ni][0] = Bb[nb * SB2 + kk + t4];
                b[ni][1] = Bb[nb * SB2 + kk + t4 + 4];
            }
#pragma unroll
            for (int mi = 0; mi < 2; mi++)
#pragma unroll
                for (int ni = 0; ni < 4; ni++)
                    mma_f16(c[mi][ni], a[mi][0], a[mi][1], a[mi][2], a[mi][3],
                            b[ni][0], b[ni][1]);
        }
        __syncthreads();
    }

    // per-row attention weights
    int   segr[2][2];
    float aw[2][2][NH];
#pragma unroll
    for (int mi = 0; mi < 2; mi++)
#pragma unroll
        for (int hf = 0; hf < 2; hf++) {
            int r = m0 + wm + mi * 16 + g4 + hf * 8;
            int seg = bidx[r] * NNODE + ridx[r];
            segr[mi][hf] = seg;
            float4 ae4 = *reinterpret_cast<const float4*>(&g_ae[(size_t)r * NH]);
            float4 iv4 = *reinterpret_cast<const float4*>(&g_invden[(size_t)seg * NH]);
            aw[mi][hf][0] = ae4.x * iv4.x;
            aw[mi][hf][1] = ae4.y * iv4.y;
            aw[mi][hf][2] = ae4.z * iv4.z;
            aw[mi][hf][3] = ae4.w * iv4.w;
        }

#pragma unroll
    for (int mi = 0; mi < 2; mi++) {
#pragma unroll
        for (int ni = 0; ni < 4; ni++) {
            int n = wn + ni * 8 + 2 * t4;
            int h = n >> 4;
            float bv0 = b2[n], bv1 = b2[n + 1];
            int rr0 = m0 + wm + mi * 16 + g4;
            int rr1 = rr0 + 8;
            float2 e0 = *reinterpret_cast<const float2*>(&edges0[(size_t)rr0 * NTOT + n]);
            float2 e1 = *reinterpret_cast<const float2*>(&edges0[(size_t)rr1 * NTOT + n]);
            float o00 = c[mi][ni][0] + bv0 + e0.x;
            float o01 = c[mi][ni][1] + bv1 + e0.y;
            float o10 = c[mi][ni][2] + bv0 + e1.x;
            float o11 = c[mi][ni][3] + bv1 + e1.y;
            *reinterpret_cast<float2*>(&Cout[(size_t)rr0 * NTOT + n]) = make_float2(o00, o01);
            *reinterpret_cast<float2*>(&Cout[(size_t)rr1 * NTOT + n]) = make_float2(o10, o11);
            float w0 = aw[mi][0][h], w1 = aw[mi][1][h];
            atomicAdd(&pooled[(size_t)segr[mi][0] * OUTD + n],     o00 * w0);
            atomicAdd(&pooled[(size_t)segr[mi][0] * OUTD + n + 1], o01 * w0);
            atomicAdd(&pooled[(size_t)segr[mi][1] * OUTD + n],     o10 * w1);
            atomicAdd(&pooled[(size_t)segr[mi][1] * OUTD + n + 1], o11 * w1);
        }
    }
}

// ---------------- entry ----------------
extern "C" void kernel_launch(void* const* d_in, const int* in_sizes, int n_in,
                              void* d_out, int out_size)
{
    const float* nodes  = (const float*)d_in[0];
    const float* edges0 = (const float*)d_in[1];
    const float* globs  = (const float*)d_in[2];
    const float* ln_g   = (const float*)d_in[3];
    const float* ln_b   = (const float*)d_in[4];
    const float* W1     = (const float*)d_in[5];
    const float* b1     = (const float*)d_in[6];
    const float* W2     = (const float*)d_in[7];
    const float* b2     = (const float*)d_in[8];
    const float* A1     = (const float*)d_in[9];
    const float* ab1    = (const float*)d_in[10];
    const float* A2     = (const float*)d_in[11];
    const float* ab2    = (const float*)d_in[12];
    const int*   bidx   = (const int*)d_in[13];
    const int*   sidx   = (const int*)d_in[14];
    const int*   ridx   = (const int*)d_in[15];

    float* out    = (float*)d_out;
    float* newe   = out;
    float* pooled = out + (size_t)EDG * OUTD;

    static bool attr_done = false;
    if (!attr_done) {
        cudaFuncSetAttribute(gemm1_fused, cudaFuncAttributeMaxDynamicSharedMemorySize, DYN_G1);
        cudaFuncSetAttribute(gemm2_fused, cudaFuncAttributeMaxDynamicSharedMemorySize, DYN_G2);
        attr_done = true;
    }

    prep_kernel<<<(NSEG * OUTD + 255) / 256, 256>>>(W1, A1, W2, ln_g, pooled);
    prep2_kernel<<<(NW + 31) / 32, 32>>>(W1, A1, b1, ab1, ln_g, ln_b, globs);
    gemm1_fused<<<dim3(5, EDG / 128), 256, DYN_G1>>>(nodes, edges0, bidx, sidx, ridx, A2, ab2);
    invden_kernel<<<(NSEG * NH + 255) / 256, 256>>>();
    gemm2_fused<<<dim3(1, EDG / 128), 256, DYN_G2>>>(b2, edges0, bidx, ridx, newe, pooled);
}